// round 12
// baseline (speedup 1.0000x reference)
#include <cuda_runtime.h>
#include <cuda_bf16.h>
#include <math.h>
#include <stdint.h>

#define T_ 8
#define NT_ 12288
#define D_ 256
#define NN_ 8192
#define NS_ 32768
#define CL_ 16
#define CD_ 64
#define CHUNK_ 2048
#define H_ 128

// dynamic smem layout for k_gemm_mma
#define SM_B 0
#define SM_U 131072
#define SM_T 131584
#define SM_SLOT 132096
#define SM_TOTAL 132608

// Scratch (device globals; zero-initialized at load; pre1 invariant restored by k_chunk)
__device__ __align__(16) float g_pre1[(size_t)T_ * NS_ * H_];   // scatter accumulator (134 MB)
__device__ float g_u[H_];                                       // sum_k beta_k * w1[k][c]
__device__ float g_t[H_];                                       // sum_k gamma_k * w1[k][c]
__device__ __align__(16) uint4 g_wq[8192];                      // fragment-packed B hi/lo (128KB)
__device__ __align__(16) float g_Spart[T_ * CL_ * 8 * H_];      // per-subblock gelu partial sums
__device__ float g_t2[T_ * CL_ * CD_];                          // post-LN chunk vectors
__device__ float g_dec[T_ * CL_ * D_];                          // decoded vectors

__device__ __forceinline__ float geluf(float v) {
    return 0.5f * v * (1.0f + erff(v * 0.70710678118654752440f));
}
__device__ __forceinline__ void red2(float* p, float a, float b) {
    asm volatile("red.global.add.v2.f32 [%0], {%1,%2};"
                 :: "l"(p), "f"(a), "f"(b) : "memory");
}
// bf16 HMMA m16n8k16, fp32 accum (legal on base compute_103 target)
__device__ __forceinline__ void mma_bf16(float* c, const uint32_t* a, uint32_t b0, uint32_t b1) {
    asm volatile(
        "mma.sync.aligned.m16n8k16.row.col.f32.bf16.bf16.f32 "
        "{%0,%1,%2,%3}, {%4,%5,%6,%7}, {%8,%9}, {%0,%1,%2,%3};"
        : "+f"(c[0]), "+f"(c[1]), "+f"(c[2]), "+f"(c[3])
        : "r"(a[0]), "r"(a[1]), "r"(a[2]), "r"(a[3]), "r"(b0), "r"(b1));
}
// split a float2 into packed bf16x2 hi and lo (x in low half)
__device__ __forceinline__ void split2(float2 p, uint32_t& hi, uint32_t& lo) {
    __nv_bfloat162 h = __floats2bfloat162_rn(p.x, p.y);
    __nv_bfloat162 l = __floats2bfloat162_rn(p.x - __bfloat162float(h.x),
                                             p.y - __bfloat162float(h.y));
    hi = *reinterpret_cast<uint32_t*>(&h);
    lo = *reinterpret_cast<uint32_t*>(&l);
}
__device__ __forceinline__ uint32_t packbf(float a, float b) {
    __nv_bfloat162 h = __floats2bfloat162_rn(a, b);
    return *reinterpret_cast<uint32_t*>(&h);
}

// no-op: launch-slot spacer so k_gemm_mma lands in ncu's profiled (4th) launch
__global__ void k_nop() {}

// ---------------------------------------------------------------------------
// K0a: fragment-packed B = (gamma.*w1)^T bf16 hi/lo.
// Quad qi = ((ks*4+g1)*16+nt)*8 + g0*4 + tg, n = nt*8+g1*2+g0, k0 = ks*16+2tg:
//   { hi(k0,k0+1), hi(k0+8,k0+9), lo(k0,k0+1), lo(k0+8,k0+9) } for column n.
// ---------------------------------------------------------------------------
__global__ void k_prep_w(const float* __restrict__ lng, const float* __restrict__ w1) {
    int qi = blockIdx.x * 256 + threadIdx.x;     // 8192 quads
    int tg = qi & 3, g0 = (qi >> 2) & 1, nt = (qi >> 3) & 15;
    int g1 = (qi >> 7) & 3, ks = qi >> 9;
    int n = nt * 8 + g1 * 2 + g0;
    int k0 = ks * 16 + 2 * tg;
    float v0 = __ldg(&lng[k0 + 0]) * __ldg(&w1[(k0 + 0) * H_ + n]);
    float v1 = __ldg(&lng[k0 + 1]) * __ldg(&w1[(k0 + 1) * H_ + n]);
    float v8 = __ldg(&lng[k0 + 8]) * __ldg(&w1[(k0 + 8) * H_ + n]);
    float v9 = __ldg(&lng[k0 + 9]) * __ldg(&w1[(k0 + 9) * H_ + n]);
    __nv_bfloat16 h0 = __float2bfloat16(v0), h1 = __float2bfloat16(v1);
    __nv_bfloat16 h8 = __float2bfloat16(v8), h9 = __float2bfloat16(v9);
    uint4 q;
    q.x = packbf(v0, v1);    // hi pair (round-to-nearest of v)
    q.y = packbf(v8, v9);
    q.z = packbf(v0 - __bfloat162float(h0), v1 - __bfloat162float(h1));
    q.w = packbf(v8 - __bfloat162float(h8), v9 - __bfloat162float(h9));
    // NOTE: q.x/q.y use RN of the pair; recompute hi consistently with lo:
    __nv_bfloat162 hp01 = __floats2bfloat162_rn(v0, v1);
    __nv_bfloat162 hp89 = __floats2bfloat162_rn(v8, v9);
    q.x = *reinterpret_cast<uint32_t*>(&hp01);
    q.y = *reinterpret_cast<uint32_t*>(&hp89);
    q.z = packbf(v0 - __bfloat162float(hp01.x), v1 - __bfloat162float(hp01.y));
    q.w = packbf(v8 - __bfloat162float(hp89.x), v9 - __bfloat162float(hp89.y));
    g_wq[qi] = q;
}

// ---------------------------------------------------------------------------
// K0b: u[c] = sum_k beta_k w1[k][c];  t[c] = sum_k gamma_k w1[k][c]
// ---------------------------------------------------------------------------
__global__ void k_prep_ut(const float* __restrict__ lng, const float* __restrict__ lnb,
                          const float* __restrict__ w1) {
    int c = threadIdx.x;   // 128
    float uu = 0.f, tt = 0.f;
    #pragma unroll 8
    for (int k = 0; k < D_; k++) {
        float w = __ldg(&w1[k * H_ + c]);
        uu += __ldg(&lnb[k]) * w;
        tt += __ldg(&lng[k]) * w;
    }
    g_u[c] = uu;
    g_t[c] = tt;
}

// ---------------------------------------------------------------------------
// K2: HMMA GEMM1. Block = 128 rows x 128 cols x K=256; warp owns 16 rows.
//     bf16-split fp32 emulation (Ah*Wh + Ah*Wl + Al*Wh). A from global with
//     in-reg split; LN stats accumulated inside the mainloop (full row covered
//     across the tg-quad; 2 shfl.xor in epilogue). B fragments: one LDS.128
//     per (nt,ks), conflict-free. LN folded + red.v2 scatter in epilogue.
// ---------------------------------------------------------------------------
__global__ void __launch_bounds__(256, 1)
k_gemm_mma(const float* __restrict__ x, const int* __restrict__ indices) {
    extern __shared__ __align__(16) char dsm[];
    const uint4* bq = reinterpret_cast<const uint4*>(dsm + SM_B);
    float* su = reinterpret_cast<float*>(dsm + SM_U);
    float* stt = reinterpret_cast<float*>(dsm + SM_T);
    int* sslot = reinterpret_cast<int*>(dsm + SM_SLOT);

    int tid = threadIdx.x;
    int warp = tid >> 5, lane = tid & 31;
    int gid = lane >> 2, tg = lane & 3;
    int rowBase = blockIdx.x * 128;
    int t = rowBase >> 13;
    int iBase = rowBase & (NN_ - 1);

    // Stage B (8192 uint4, coalesced) + u/t/slots
    {
        uint4* db = reinterpret_cast<uint4*>(dsm + SM_B);
        #pragma unroll
        for (int i = 0; i < 32; i++) db[tid + i * 256] = g_wq[tid + i * 256];
    }
    if (tid < 128) {
        su[tid] = g_u[tid];
        stt[tid] = g_t[tid];
        sslot[tid] = __ldg(&indices[t * NN_ + iBase + tid]);
    }
    __syncthreads();

    // Mainloop: no syncs; A from global with in-reg bf16 split + fused stats
    const float2* xr0 = reinterpret_cast<const float2*>(x)
                      + ((size_t)t * NT_ + iBase + warp * 16 + gid) * 128;
    const float2* xr8 = xr0 + 8 * 128;

    float acc[16][4];
    #pragma unroll
    for (int nt = 0; nt < 16; nt++)
        #pragma unroll
        for (int c = 0; c < 4; c++) acc[nt][c] = 0.f;

    float s0 = 0.f, q0 = 0.f, s1 = 0.f, q1 = 0.f;
    int fb = (gid >> 1) * 128 + (gid & 1) * 4 + tg;   // fragment base (uint4 idx)

    #pragma unroll 2
    for (int ks = 0; ks < 16; ks++) {
        float2 p00 = xr0[ks * 8 + tg], p08 = xr0[ks * 8 + tg + 4];
        float2 p80 = xr8[ks * 8 + tg], p88 = xr8[ks * 8 + tg + 4];
        s0 += (p00.x + p00.y) + (p08.x + p08.y);
        q0 += (p00.x * p00.x + p00.y * p00.y) + (p08.x * p08.x + p08.y * p08.y);
        s1 += (p80.x + p80.y) + (p88.x + p88.y);
        q1 += (p80.x * p80.x + p80.y * p80.y) + (p88.x * p88.x + p88.y * p88.y);
        uint32_t ah[4], al[4];
        split2(p00, ah[0], al[0]);
        split2(p80, ah[1], al[1]);
        split2(p08, ah[2], al[2]);
        split2(p88, ah[3], al[3]);
        const uint4* bks = bq + ks * 512 + fb;
        #pragma unroll
        for (int nt = 0; nt < 16; nt++) {
            uint4 f = bks[nt * 8];
            mma_bf16(acc[nt], ah, f.x, f.y);
            mma_bf16(acc[nt], ah, f.z, f.w);
            mma_bf16(acc[nt], al, f.x, f.y);
        }
    }

    // Epilogue: reduce stats across tg-quad, fold LN, red.v2 scatter
    {
        s0 += __shfl_xor_sync(0xffffffffu, s0, 1);
        s0 += __shfl_xor_sync(0xffffffffu, s0, 2);
        q0 += __shfl_xor_sync(0xffffffffu, q0, 1);
        q0 += __shfl_xor_sync(0xffffffffu, q0, 2);
        s1 += __shfl_xor_sync(0xffffffffu, s1, 1);
        s1 += __shfl_xor_sync(0xffffffffu, s1, 2);
        q1 += __shfl_xor_sync(0xffffffffu, q1, 1);
        q1 += __shfl_xor_sync(0xffffffffu, q1, 2);
        float mean0 = s0 * (1.0f / 256.0f);
        float rs0 = rsqrtf(q0 * (1.0f / 256.0f) - mean0 * mean0 + 1e-5f);
        float mean1 = s1 * (1.0f / 256.0f);
        float rs1 = rsqrtf(q1 * (1.0f / 256.0f) - mean1 * mean1 + 1e-5f);
        float mr0 = mean0 * rs0, mr1 = mean1 * rs1;
        int r0 = warp * 16 + gid;
        float* d0 = g_pre1 + ((size_t)t * NS_ + sslot[r0]) * H_;
        float* d1 = g_pre1 + ((size_t)t * NS_ + sslot[r0 + 8]) * H_;
        #pragma unroll
        for (int nt = 0; nt < 16; nt++) {
            int c = nt * 8 + 2 * tg;
            float u0 = su[c], u1 = su[c + 1];
            float t0 = stt[c], t1 = stt[c + 1];
            red2(d0 + c, rs0 * acc[nt][0] + u0 - mr0 * t0,
                         rs0 * acc[nt][1] + u1 - mr0 * t1);
            red2(d1 + c, rs1 * acc[nt][2] + u0 - mr1 * t0,
                         rs1 * acc[nt][3] + u1 - mr1 * t1);
        }
    }
}

// ---------------------------------------------------------------------------
// K3: dense streaming gelu-sum over pre1; zero rows (warp ballot) skip gelu
//     (contribution = zc * gelu(b1)); touched rows are re-zeroed.
// ---------------------------------------------------------------------------
__global__ void __launch_bounds__(256) k_chunk(const float* __restrict__ b1) {
    __shared__ float part[8][128];
    int tid = threadIdx.x;
    int warp = tid >> 5, lane = tid & 31;

    float4 b1v = reinterpret_cast<const float4*>(b1)[lane];
    float4 acc = make_float4(0.f, 0.f, 0.f, 0.f);
    float4 z4 = make_float4(0.f, 0.f, 0.f, 0.f);
    int zc = 0;

    float4* basep = reinterpret_cast<float4*>(g_pre1) + ((size_t)blockIdx.x * 256 + warp * 32) * 32;

    #pragma unroll
    for (int i0 = 0; i0 < 32; i0 += 4) {
        float4 v0 = basep[(i0 + 0) * 32 + lane];
        float4 v1 = basep[(i0 + 1) * 32 + lane];
        float4 v2 = basep[(i0 + 2) * 32 + lane];
        float4 v3 = basep[(i0 + 3) * 32 + lane];
        #pragma unroll
        for (int u = 0; u < 4; u++) {
            float4 v = (u == 0) ? v0 : (u == 1) ? v1 : (u == 2) ? v2 : v3;
            bool nz = (v.x != 0.f) | (v.y != 0.f) | (v.z != 0.f) | (v.w != 0.f);
            unsigned m = __ballot_sync(0xffffffffu, nz);
            if (m) {
                acc.x += geluf(v.x + b1v.x);
                acc.y += geluf(v.y + b1v.y);
                acc.z += geluf(v.z + b1v.z);
                acc.w += geluf(v.w + b1v.w);
                basep[(i0 + u) * 32 + lane] = z4;
            } else {
                zc++;
            }
        }
    }

    float fzc = (float)zc;
    part[warp][lane * 4 + 0] = acc.x + fzc * geluf(b1v.x);
    part[warp][lane * 4 + 1] = acc.y + fzc * geluf(b1v.y);
    part[warp][lane * 4 + 2] = acc.z + fzc * geluf(b1v.z);
    part[warp][lane * 4 + 3] = acc.w + fzc * geluf(b1v.w);
    __syncthreads();
    if (tid < 128) {
        float s = 0.f;
        #pragma unroll
        for (int w = 0; w < 8; w++) s += part[w][tid];
        g_Spart[blockIdx.x * 128 + tid] = s;
    }
}

// ---------------------------------------------------------------------------
// K4: per t: reduce partials -> S ; comp = S@w2 + CHUNK*b2 ; LN(1024) ;
//     per-chunk LN(64) -> g_t2
// ---------------------------------------------------------------------------
__global__ void k_lnf(const float* __restrict__ w2, const float* __restrict__ b2,
                      const float* __restrict__ lnfg, const float* __restrict__ lnfb,
                      const float* __restrict__ lndg, const float* __restrict__ lndb) {
    __shared__ float sS[CL_ * H_];
    __shared__ float sc[CL_ * CD_];
    __shared__ float redbuf[16];
    __shared__ float bcast[2];

    int tid = threadIdx.x, lane = tid & 31, warp = tid >> 5;
    int t = blockIdx.x;

    const float* sp = g_Spart + t * CL_ * 8 * H_;
    for (int o = tid; o < CL_ * H_; o += 256) {
        int c = o >> 7, k = o & 127;
        float s = 0.f;
        #pragma unroll
        for (int sub = 0; sub < 8; sub++) s += sp[(c * 8 + sub) * H_ + k];
        sS[o] = s;
    }
    __syncthreads();

    {
        int jj = tid & 63, cg = tid >> 6;
        float a0 = 0.f, a1 = 0.f, a2 = 0.f, a3 = 0.f;
        for (int k = 0; k < H_; k++) {
            float w = w2[k * 64 + jj];
            a0 += sS[(cg) * H_ + k] * w;
            a1 += sS[(cg + 4) * H_ + k] * w;
            a2 += sS[(cg + 8) * H_ + k] * w;
            a3 += sS[(cg + 12) * H_ + k] * w;
        }
        float bb = (float)CHUNK_ * b2[jj];
        sc[(cg) * 64 + jj] = a0 + bb;
        sc[(cg + 4) * 64 + jj] = a1 + bb;
        sc[(cg + 8) * 64 + jj] = a2 + bb;
        sc[(cg + 12) * 64 + jj] = a3 + bb;
    }
    __syncthreads();

    float s = 0.f, q = 0.f;
    for (int o = tid; o < 1024; o += 256) { float v = sc[o]; s += v; q += v * v; }
    #pragma unroll
    for (int m = 16; m; m >>= 1) {
        s += __shfl_xor_sync(0xffffffffu, s, m);
        q += __shfl_xor_sync(0xffffffffu, q, m);
    }
    if (lane == 0) { redbuf[warp] = s; redbuf[8 + warp] = q; }
    __syncthreads();
    if (tid == 0) {
        float S2 = 0.f, Q2 = 0.f;
        #pragma unroll
        for (int w = 0; w < 8; w++) { S2 += redbuf[w]; Q2 += redbuf[8 + w]; }
        float m = S2 * (1.0f / 1024.0f);
        float var = Q2 * (1.0f / 1024.0f) - m * m;
        bcast[0] = m;
        bcast[1] = rsqrtf(var + 1e-5f);
    }
    __syncthreads();
    float m1 = bcast[0], rs1 = bcast[1];
    for (int o = tid; o < 1024; o += 256) sc[o] = (sc[o] - m1) * rs1 * lnfg[o] + lnfb[o];
    __syncthreads();

    #pragma unroll
    for (int gi = 0; gi < 2; gi++) {
        int g = warp * 2 + gi;
        float v0 = sc[g * 64 + lane], v1 = sc[g * 64 + 32 + lane];
        float gs = v0 + v1, gq = v0 * v0 + v1 * v1;
        #pragma unroll
        for (int mm = 16; mm; mm >>= 1) {
            gs += __shfl_xor_sync(0xffffffffu, gs, mm);
            gq += __shfl_xor_sync(0xffffffffu, gq, mm);
        }
        float gm = gs * (1.0f / 64.0f);
        float gv = gq * (1.0f / 64.0f) - gm * gm;
        float grs = rsqrtf(gv + 1e-5f);
        g_t2[t * 1024 + g * 64 + lane] = (v0 - gm) * grs * lndg[lane] + lndb[lane];
        g_t2[t * 1024 + g * 64 + 32 + lane] =
            (v1 - gm) * grs * lndg[lane + 32] + lndb[lane + 32];
    }
}

// ---------------------------------------------------------------------------
// K5: decoder MLP, one block per (t, chunk): 64 -> gelu(128) -> 256
// ---------------------------------------------------------------------------
__global__ void k_dec(const float* __restrict__ dw1, const float* __restrict__ db1,
                      const float* __restrict__ dw2, const float* __restrict__ db2) {
    __shared__ float t2s[CD_];
    __shared__ float d1[H_];
    int tid = threadIdx.x;
    int row = blockIdx.x;

    if (tid < CD_) t2s[tid] = g_t2[row * CD_ + tid];
    __syncthreads();

    if (tid < H_) {
        float a0 = 0.f, a1 = 0.f;
        #pragma unroll
        for (int j = 0; j < CD_; j += 2) {
            a0 += t2s[j] * __ldg(&dw1[j * H_ + tid]);
            a1 += t2s[j + 1] * __ldg(&dw1[(j + 1) * H_ + tid]);
        }
        d1[tid] = geluf(a0 + a1 + db1[tid]);
    }
    __syncthreads();

    float o0 = 0.f, o1 = 0.f;
    #pragma unroll
    for (int k = 0; k < H_; k += 2) {
        o0 += d1[k] * __ldg(&dw2[k * D_ + tid]);
        o1 += d1[k + 1] * __ldg(&dw2[(k + 1) * D_ + tid]);
    }
    g_dec[row * D_ + tid] = o0 + o1 + db2[tid];
}

// ---------------------------------------------------------------------------
// K6: output gather (rows < 8192: broadcast decoded chunk row; else zeros)
// ---------------------------------------------------------------------------
__global__ void k_gather(const int* __restrict__ indices, float4* __restrict__ out) {
    int idx = blockIdx.x * 256 + threadIdx.x;
    int r = idx >> 6, q = idx & 63;
    int t = r / NT_;
    int i = r - t * NT_;
    float4 v;
    if (i < NN_) {
        int c = indices[t * NN_ + i] >> 11;
        v = reinterpret_cast<const float4*>(g_dec)[(t * CL_ + c) * 64 + q];
    } else {
        v = make_float4(0.f, 0.f, 0.f, 0.f);
    }
    out[idx] = v;
}

extern "C" void kernel_launch(void* const* d_in, const int* in_sizes, int n_in,
                              void* d_out, int out_size) {
    const float* x    = (const float*)d_in[0];
    const int*   ind  = (const int*)d_in[1];
    const float* ln1g = (const float*)d_in[2];
    const float* ln1b = (const float*)d_in[3];
    const float* w1   = (const float*)d_in[4];
    const float* b1   = (const float*)d_in[5];
    const float* w2   = (const float*)d_in[6];
    const float* b2   = (const float*)d_in[7];
    const float* lnfg = (const float*)d_in[8];
    const float* lnfb = (const float*)d_in[9];
    const float* lndg = (const float*)d_in[10];
    const float* lndb = (const float*)d_in[11];
    const float* dw1  = (const float*)d_in[12];
    const float* db1  = (const float*)d_in[13];
    const float* dw2  = (const float*)d_in[14];
    const float* db2  = (const float*)d_in[15];

    cudaFuncSetAttribute(k_gemm_mma, cudaFuncAttributeMaxDynamicSharedMemorySize, SM_TOTAL);

    k_prep_w<<<32, 256>>>(ln1g, w1);                               // launch 1
    k_prep_ut<<<1, 128>>>(ln1g, ln1b, w1);                         // launch 2
    k_nop<<<1, 32>>>();                                            // launch 3
    k_gemm_mma<<<T_ * NN_ / 128, 256, SM_TOTAL>>>(x, ind);         // launch 4 (profiled)
    k_chunk<<<T_ * NS_ / 256, 256>>>(b1);
    k_lnf<<<T_, 256>>>(w2, b2, lnfg, lnfb, lndg, lndb);
    k_dec<<<T_ * CL_, 256>>>(dw1, db1, dw2, db2);
    k_gather<<<(T_ * NT_ * 64) / 256, 256>>>(ind, (float4*)d_out);
}

// round 14
// speedup vs baseline: 1.2526x; 1.2526x over previous
#include <cuda_runtime.h>
#include <cuda_bf16.h>
#include <math.h>
#include <stdint.h>

#define T_ 8
#define NT_ 12288
#define D_ 256
#define NN_ 8192
#define NS_ 32768
#define CL_ 16
#define CD_ 64
#define CHUNK_ 2048
#define H_ 128

// dynamic smem layout for k_gemm_mma (512 threads / 256 rows per block)
#define SM_B 0
#define SM_U 131072
#define SM_T 131584
#define SM_SLOT 132096
#define SM_TOTAL 133120

// Scratch (device globals; zero-initialized at load; pre1 invariant restored by k_chunk)
__device__ __align__(16) float g_pre1[(size_t)T_ * NS_ * H_];   // scatter accumulator (134 MB)
__device__ float g_u[H_];                                       // sum_k beta_k * w1[k][c]
__device__ float g_t[H_];                                       // sum_k gamma_k * w1[k][c]
__device__ __align__(16) uint4 g_wq[8192];                      // fragment-packed B hi/lo (128KB)
__device__ __align__(16) float g_Spart[T_ * CL_ * 8 * H_];      // per-subblock gelu partial sums
__device__ float g_t2[T_ * CL_ * CD_];                          // post-LN chunk vectors
__device__ float g_dec[T_ * CL_ * D_];                          // decoded vectors

__device__ __forceinline__ float geluf(float v) {
    return 0.5f * v * (1.0f + erff(v * 0.70710678118654752440f));
}
__device__ __forceinline__ void red2(float* p, float a, float b) {
    asm volatile("red.global.add.v2.f32 [%0], {%1,%2};"
                 :: "l"(p), "f"(a), "f"(b) : "memory");
}
// bf16 HMMA m16n8k16, fp32 accum (legal on base compute_103 target)
__device__ __forceinline__ void mma_bf16(float* c, const uint32_t* a, uint32_t b0, uint32_t b1) {
    asm volatile(
        "mma.sync.aligned.m16n8k16.row.col.f32.bf16.bf16.f32 "
        "{%0,%1,%2,%3}, {%4,%5,%6,%7}, {%8,%9}, {%0,%1,%2,%3};"
        : "+f"(c[0]), "+f"(c[1]), "+f"(c[2]), "+f"(c[3])
        : "r"(a[0]), "r"(a[1]), "r"(a[2]), "r"(a[3]), "r"(b0), "r"(b1));
}
// split a float2 into packed bf16x2 hi and lo (x in low half)
__device__ __forceinline__ void split2(float2 p, uint32_t& hi, uint32_t& lo) {
    __nv_bfloat162 h = __floats2bfloat162_rn(p.x, p.y);
    __nv_bfloat162 l = __floats2bfloat162_rn(p.x - __bfloat162float(h.x),
                                             p.y - __bfloat162float(h.y));
    hi = *reinterpret_cast<uint32_t*>(&h);
    lo = *reinterpret_cast<uint32_t*>(&l);
}
__device__ __forceinline__ uint32_t packbf(float a, float b) {
    __nv_bfloat162 h = __floats2bfloat162_rn(a, b);
    return *reinterpret_cast<uint32_t*>(&h);
}

// no-op: launch-slot spacer so k_gemm_mma lands in ncu's profiled (4th) launch
__global__ void k_nop() {}

// ---------------------------------------------------------------------------
// K0a: fragment-packed B = (gamma.*w1)^T bf16 hi/lo.
// Quad qi = ((ks*4+g1)*16+nt)*8 + g0*4 + tg, n = nt*8+g1*2+g0, k0 = ks*16+2tg:
//   { hi(k0,k0+1), hi(k0+8,k0+9), lo(k0,k0+1), lo(k0+8,k0+9) } for column n.
// ---------------------------------------------------------------------------
__global__ void k_prep_w(const float* __restrict__ lng, const float* __restrict__ w1) {
    int qi = blockIdx.x * 256 + threadIdx.x;     // 8192 quads
    int tg = qi & 3, g0 = (qi >> 2) & 1, nt = (qi >> 3) & 15;
    int g1 = (qi >> 7) & 3, ks = qi >> 9;
    int n = nt * 8 + g1 * 2 + g0;
    int k0 = ks * 16 + 2 * tg;
    float v0 = __ldg(&lng[k0 + 0]) * __ldg(&w1[(k0 + 0) * H_ + n]);
    float v1 = __ldg(&lng[k0 + 1]) * __ldg(&w1[(k0 + 1) * H_ + n]);
    float v8 = __ldg(&lng[k0 + 8]) * __ldg(&w1[(k0 + 8) * H_ + n]);
    float v9 = __ldg(&lng[k0 + 9]) * __ldg(&w1[(k0 + 9) * H_ + n]);
    __nv_bfloat162 hp01 = __floats2bfloat162_rn(v0, v1);
    __nv_bfloat162 hp89 = __floats2bfloat162_rn(v8, v9);
    uint4 q;
    q.x = *reinterpret_cast<uint32_t*>(&hp01);
    q.y = *reinterpret_cast<uint32_t*>(&hp89);
    q.z = packbf(v0 - __bfloat162float(hp01.x), v1 - __bfloat162float(hp01.y));
    q.w = packbf(v8 - __bfloat162float(hp89.x), v9 - __bfloat162float(hp89.y));
    g_wq[qi] = q;
}

// ---------------------------------------------------------------------------
// K0b: u[c] = sum_k beta_k w1[k][c];  t[c] = sum_k gamma_k w1[k][c]
// ---------------------------------------------------------------------------
__global__ void k_prep_ut(const float* __restrict__ lng, const float* __restrict__ lnb,
                          const float* __restrict__ w1) {
    int c = threadIdx.x;   // 128
    float uu = 0.f, tt = 0.f;
    #pragma unroll 8
    for (int k = 0; k < D_; k++) {
        float w = __ldg(&w1[k * H_ + c]);
        uu += __ldg(&lnb[k]) * w;
        tt += __ldg(&lng[k]) * w;
    }
    g_u[c] = uu;
    g_t[c] = tt;
}

// ---------------------------------------------------------------------------
// K2: HMMA GEMM1. Block = 256 rows x 128 cols x K=256; 16 warps (512 thr),
//     each warp 16 rows x 128 cols. bf16-split fp32 emulation
//     (Ah*Wh + Ah*Wl + Al*Wh). A from global with in-reg split; LN stats
//     fused in the mainloop (tg-quad covers the row; 2 shfl.xor in epilogue).
//     B fragment-packed in smem, one LDS.128 per (nt,ks). 16 warps/SM for
//     latency hiding. LN folded + red.v2 scatter in epilogue.
// ---------------------------------------------------------------------------
__global__ void __launch_bounds__(512, 1)
k_gemm_mma(const float* __restrict__ x, const int* __restrict__ indices) {
    extern __shared__ __align__(16) char dsm[];
    const uint4* bq = reinterpret_cast<const uint4*>(dsm + SM_B);
    float* su = reinterpret_cast<float*>(dsm + SM_U);
    float* stt = reinterpret_cast<float*>(dsm + SM_T);
    int* sslot = reinterpret_cast<int*>(dsm + SM_SLOT);

    int tid = threadIdx.x;
    int warp = tid >> 5, lane = tid & 31;
    int gid = lane >> 2, tg = lane & 3;
    int rowBase = blockIdx.x * 256;
    int t = rowBase >> 13;
    int iBase = rowBase & (NN_ - 1);

    // Stage B (8192 uint4, coalesced) + u/t/slots
    {
        uint4* db = reinterpret_cast<uint4*>(dsm + SM_B);
        #pragma unroll
        for (int i = 0; i < 16; i++) db[tid + i * 512] = g_wq[tid + i * 512];
    }
    if (tid < 256) {
        if (tid < 128) { su[tid] = g_u[tid]; stt[tid] = g_t[tid]; }
        sslot[tid] = __ldg(&indices[t * NN_ + iBase + tid]);
    }
    __syncthreads();

    // Mainloop: no syncs; A from global with in-reg bf16 split + fused stats
    const float2* xr0 = reinterpret_cast<const float2*>(x)
                      + ((size_t)t * NT_ + iBase + warp * 16 + gid) * 128;
    const float2* xr8 = xr0 + 8 * 128;

    float acc[16][4];
    #pragma unroll
    for (int nt = 0; nt < 16; nt++)
        #pragma unroll
        for (int c = 0; c < 4; c++) acc[nt][c] = 0.f;

    float s0 = 0.f, q0 = 0.f, s1 = 0.f, q1 = 0.f;
    int fb = (gid >> 1) * 128 + (gid & 1) * 4 + tg;   // fragment base (uint4 idx)

    #pragma unroll 2
    for (int ks = 0; ks < 16; ks++) {
        float2 p00 = xr0[ks * 8 + tg], p08 = xr0[ks * 8 + tg + 4];
        float2 p80 = xr8[ks * 8 + tg], p88 = xr8[ks * 8 + tg + 4];
        s0 += (p00.x + p00.y) + (p08.x + p08.y);
        q0 += (p00.x * p00.x + p00.y * p00.y) + (p08.x * p08.x + p08.y * p08.y);
        s1 += (p80.x + p80.y) + (p88.x + p88.y);
        q1 += (p80.x * p80.x + p80.y * p80.y) + (p88.x * p88.x + p88.y * p88.y);
        uint32_t ah[4], al[4];
        split2(p00, ah[0], al[0]);
        split2(p80, ah[1], al[1]);
        split2(p08, ah[2], al[2]);
        split2(p88, ah[3], al[3]);
        const uint4* bks = bq + ks * 512 + fb;
        #pragma unroll
        for (int nt = 0; nt < 16; nt++) {
            uint4 f = bks[nt * 8];
            mma_bf16(acc[nt], ah, f.x, f.y);
            mma_bf16(acc[nt], ah, f.z, f.w);
            mma_bf16(acc[nt], al, f.x, f.y);
        }
    }

    // Epilogue: reduce stats across tg-quad, fold LN, red.v2 scatter
    {
        s0 += __shfl_xor_sync(0xffffffffu, s0, 1);
        s0 += __shfl_xor_sync(0xffffffffu, s0, 2);
        q0 += __shfl_xor_sync(0xffffffffu, q0, 1);
        q0 += __shfl_xor_sync(0xffffffffu, q0, 2);
        s1 += __shfl_xor_sync(0xffffffffu, s1, 1);
        s1 += __shfl_xor_sync(0xffffffffu, s1, 2);
        q1 += __shfl_xor_sync(0xffffffffu, q1, 1);
        q1 += __shfl_xor_sync(0xffffffffu, q1, 2);
        float mean0 = s0 * (1.0f / 256.0f);
        float rs0 = rsqrtf(q0 * (1.0f / 256.0f) - mean0 * mean0 + 1e-5f);
        float mean1 = s1 * (1.0f / 256.0f);
        float rs1 = rsqrtf(q1 * (1.0f / 256.0f) - mean1 * mean1 + 1e-5f);
        float mr0 = mean0 * rs0, mr1 = mean1 * rs1;
        int r0 = warp * 16 + gid;
        float* d0 = g_pre1 + ((size_t)t * NS_ + sslot[r0]) * H_;
        float* d1 = g_pre1 + ((size_t)t * NS_ + sslot[r0 + 8]) * H_;
        #pragma unroll
        for (int nt = 0; nt < 16; nt++) {
            int c = nt * 8 + 2 * tg;
            float u0 = su[c], u1 = su[c + 1];
            float t0 = stt[c], t1 = stt[c + 1];
            red2(d0 + c, rs0 * acc[nt][0] + u0 - mr0 * t0,
                         rs0 * acc[nt][1] + u1 - mr0 * t1);
            red2(d1 + c, rs1 * acc[nt][2] + u0 - mr1 * t0,
                         rs1 * acc[nt][3] + u1 - mr1 * t1);
        }
    }
}

// ---------------------------------------------------------------------------
// K3: dense streaming gelu-sum over pre1; zero rows (warp ballot) skip gelu
//     (contribution = zc * gelu(b1)); touched rows are re-zeroed.
// ---------------------------------------------------------------------------
__global__ void __launch_bounds__(256) k_chunk(const float* __restrict__ b1) {
    __shared__ float part[8][128];
    int tid = threadIdx.x;
    int warp = tid >> 5, lane = tid & 31;

    float4 b1v = reinterpret_cast<const float4*>(b1)[lane];
    float4 acc = make_float4(0.f, 0.f, 0.f, 0.f);
    float4 z4 = make_float4(0.f, 0.f, 0.f, 0.f);
    int zc = 0;

    float4* basep = reinterpret_cast<float4*>(g_pre1) + ((size_t)blockIdx.x * 256 + warp * 32) * 32;

    #pragma unroll
    for (int i0 = 0; i0 < 32; i0 += 4) {
        float4 v0 = basep[(i0 + 0) * 32 + lane];
        float4 v1 = basep[(i0 + 1) * 32 + lane];
        float4 v2 = basep[(i0 + 2) * 32 + lane];
        float4 v3 = basep[(i0 + 3) * 32 + lane];
        #pragma unroll
        for (int u = 0; u < 4; u++) {
            float4 v = (u == 0) ? v0 : (u == 1) ? v1 : (u == 2) ? v2 : v3;
            bool nz = (v.x != 0.f) | (v.y != 0.f) | (v.z != 0.f) | (v.w != 0.f);
            unsigned m = __ballot_sync(0xffffffffu, nz);
            if (m) {
                acc.x += geluf(v.x + b1v.x);
                acc.y += geluf(v.y + b1v.y);
                acc.z += geluf(v.z + b1v.z);
                acc.w += geluf(v.w + b1v.w);
                basep[(i0 + u) * 32 + lane] = z4;
            } else {
                zc++;
            }
        }
    }

    float fzc = (float)zc;
    part[warp][lane * 4 + 0] = acc.x + fzc * geluf(b1v.x);
    part[warp][lane * 4 + 1] = acc.y + fzc * geluf(b1v.y);
    part[warp][lane * 4 + 2] = acc.z + fzc * geluf(b1v.z);
    part[warp][lane * 4 + 3] = acc.w + fzc * geluf(b1v.w);
    __syncthreads();
    if (tid < 128) {
        float s = 0.f;
        #pragma unroll
        for (int w = 0; w < 8; w++) s += part[w][tid];
        g_Spart[blockIdx.x * 128 + tid] = s;
    }
}

// ---------------------------------------------------------------------------
// K4: per t: reduce partials -> S ; comp = S@w2 + CHUNK*b2 ; LN(1024) ;
//     per-chunk LN(64) -> g_t2
// ---------------------------------------------------------------------------
__global__ void k_lnf(const float* __restrict__ w2, const float* __restrict__ b2,
                      const float* __restrict__ lnfg, const float* __restrict__ lnfb,
                      const float* __restrict__ lndg, const float* __restrict__ lndb) {
    __shared__ float sS[CL_ * H_];
    __shared__ float sc[CL_ * CD_];
    __shared__ float redbuf[16];
    __shared__ float bcast[2];

    int tid = threadIdx.x, lane = tid & 31, warp = tid >> 5;
    int t = blockIdx.x;

    const float* sp = g_Spart + t * CL_ * 8 * H_;
    for (int o = tid; o < CL_ * H_; o += 256) {
        int c = o >> 7, k = o & 127;
        float s = 0.f;
        #pragma unroll
        for (int sub = 0; sub < 8; sub++) s += sp[(c * 8 + sub) * H_ + k];
        sS[o] = s;
    }
    __syncthreads();

    {
        int jj = tid & 63, cg = tid >> 6;
        float a0 = 0.f, a1 = 0.f, a2 = 0.f, a3 = 0.f;
        for (int k = 0; k < H_; k++) {
            float w = w2[k * 64 + jj];
            a0 += sS[(cg) * H_ + k] * w;
            a1 += sS[(cg + 4) * H_ + k] * w;
            a2 += sS[(cg + 8) * H_ + k] * w;
            a3 += sS[(cg + 12) * H_ + k] * w;
        }
        float bb = (float)CHUNK_ * b2[jj];
        sc[(cg) * 64 + jj] = a0 + bb;
        sc[(cg + 4) * 64 + jj] = a1 + bb;
        sc[(cg + 8) * 64 + jj] = a2 + bb;
        sc[(cg + 12) * 64 + jj] = a3 + bb;
    }
    __syncthreads();

    float s = 0.f, q = 0.f;
    for (int o = tid; o < 1024; o += 256) { float v = sc[o]; s += v; q += v * v; }
    #pragma unroll
    for (int m = 16; m; m >>= 1) {
        s += __shfl_xor_sync(0xffffffffu, s, m);
        q += __shfl_xor_sync(0xffffffffu, q, m);
    }
    if (lane == 0) { redbuf[warp] = s; redbuf[8 + warp] = q; }
    __syncthreads();
    if (tid == 0) {
        float S2 = 0.f, Q2 = 0.f;
        #pragma unroll
        for (int w = 0; w < 8; w++) { S2 += redbuf[w]; Q2 += redbuf[8 + w]; }
        float m = S2 * (1.0f / 1024.0f);
        float var = Q2 * (1.0f / 1024.0f) - m * m;
        bcast[0] = m;
        bcast[1] = rsqrtf(var + 1e-5f);
    }
    __syncthreads();
    float m1 = bcast[0], rs1 = bcast[1];
    for (int o = tid; o < 1024; o += 256) sc[o] = (sc[o] - m1) * rs1 * lnfg[o] + lnfb[o];
    __syncthreads();

    #pragma unroll
    for (int gi = 0; gi < 2; gi++) {
        int g = warp * 2 + gi;
        float v0 = sc[g * 64 + lane], v1 = sc[g * 64 + 32 + lane];
        float gs = v0 + v1, gq = v0 * v0 + v1 * v1;
        #pragma unroll
        for (int mm = 16; mm; mm >>= 1) {
            gs += __shfl_xor_sync(0xffffffffu, gs, mm);
            gq += __shfl_xor_sync(0xffffffffu, gq, mm);
        }
        float gm = gs * (1.0f / 64.0f);
        float gv = gq * (1.0f / 64.0f) - gm * gm;
        float grs = rsqrtf(gv + 1e-5f);
        g_t2[t * 1024 + g * 64 + lane] = (v0 - gm) * grs * lndg[lane] + lndb[lane];
        g_t2[t * 1024 + g * 64 + 32 + lane] =
            (v1 - gm) * grs * lndg[lane + 32] + lndb[lane + 32];
    }
}

// ---------------------------------------------------------------------------
// K5: decoder MLP, one block per (t, chunk): 64 -> gelu(128) -> 256
// ---------------------------------------------------------------------------
__global__ void k_dec(const float* __restrict__ dw1, const float* __restrict__ db1,
                      const float* __restrict__ dw2, const float* __restrict__ db2) {
    __shared__ float t2s[CD_];
    __shared__ float d1[H_];
    int tid = threadIdx.x;
    int row = blockIdx.x;

    if (tid < CD_) t2s[tid] = g_t2[row * CD_ + tid];
    __syncthreads();

    if (tid < H_) {
        float a0 = 0.f, a1 = 0.f;
        #pragma unroll
        for (int j = 0; j < CD_; j += 2) {
            a0 += t2s[j] * __ldg(&dw1[j * H_ + tid]);
            a1 += t2s[j + 1] * __ldg(&dw1[(j + 1) * H_ + tid]);
        }
        d1[tid] = geluf(a0 + a1 + db1[tid]);
    }
    __syncthreads();

    float o0 = 0.f, o1 = 0.f;
    #pragma unroll
    for (int k = 0; k < H_; k += 2) {
        o0 += d1[k] * __ldg(&dw2[k * D_ + tid]);
        o1 += d1[k + 1] * __ldg(&dw2[(k + 1) * D_ + tid]);
    }
    g_dec[row * D_ + tid] = o0 + o1 + db2[tid];
}

// ---------------------------------------------------------------------------
// K6: output gather (rows < 8192: broadcast decoded chunk row; else zeros)
// ---------------------------------------------------------------------------
__global__ void k_gather(const int* __restrict__ indices, float4* __restrict__ out) {
    int idx = blockIdx.x * 256 + threadIdx.x;
    int r = idx >> 6, q = idx & 63;
    int t = r / NT_;
    int i = r - t * NT_;
    float4 v;
    if (i < NN_) {
        int c = indices[t * NN_ + i] >> 11;
        v = reinterpret_cast<const float4*>(g_dec)[(t * CL_ + c) * 64 + q];
    } else {
        v = make_float4(0.f, 0.f, 0.f, 0.f);
    }
    out[idx] = v;
}

extern "C" void kernel_launch(void* const* d_in, const int* in_sizes, int n_in,
                              void* d_out, int out_size) {
    const float* x    = (const float*)d_in[0];
    const int*   ind  = (const int*)d_in[1];
    const float* ln1g = (const float*)d_in[2];
    const float* ln1b = (const float*)d_in[3];
    const float* w1   = (const float*)d_in[4];
    const float* b1   = (const float*)d_in[5];
    const float* w2   = (const float*)d_in[6];
    const float* b2   = (const float*)d_in[7];
    const float* lnfg = (const float*)d_in[8];
    const float* lnfb = (const float*)d_in[9];
    const float* lndg = (const float*)d_in[10];
    const float* lndb = (const float*)d_in[11];
    const float* dw1  = (const float*)d_in[12];
    const float* db1  = (const float*)d_in[13];
    const float* dw2  = (const float*)d_in[14];
    const float* db2  = (const float*)d_in[15];

    cudaFuncSetAttribute(k_gemm_mma, cudaFuncAttributeMaxDynamicSharedMemorySize, SM_TOTAL);

    k_prep_w<<<32, 256>>>(ln1g, w1);                               // launch 1
    k_prep_ut<<<1, 128>>>(ln1g, ln1b, w1);                         // launch 2
    k_nop<<<1, 32>>>();                                            // launch 3
    k_gemm_mma<<<T_ * NN_ / 256, 512, SM_TOTAL>>>(x, ind);         // launch 4 (profiled)
    k_chunk<<<T_ * NS_ / 256, 256>>>(b1);
    k_lnf<<<T_, 256>>>(w2, b2, lnfg, lnfb, lndg, lndb);
    k_dec<<<T_ * CL_, 256>>>(dw1, db1, dw2, db2);
    k_gather<<<(T_ * NT_ * 64) / 256, 256>>>(ind, (float4*)d_out);
}